// round 1
// baseline (speedup 1.0000x reference)
#include <cuda_runtime.h>
#include <math.h>

#define B_ 2
#define T_ 2048
#define D_ 2048
#define NH 16
#define KH 4
#define HD 128

// Scratch (static device globals — no allocation allowed)
__device__ float g_Q[(size_t)B_ * T_ * NH * HD];     // (B,T,N,H)
__device__ float g_K[(size_t)B_ * T_ * KH * HD];     // (B,T,K,H)
__device__ float g_V[(size_t)B_ * T_ * KH * HD];     // (B,T,K,H)
__device__ float g_attn[(size_t)B_ * T_ * NH * HD];  // (B,T,N,H)

// ----------------------------------------------------------------------------
// Tiled fp32 SGEMM: C[M,N] = A[M,Kd] * B[Kd,N], all row-major.
// 64x64 tile, BK=16, 256 threads, 4x4 accum per thread.
// ----------------------------------------------------------------------------
__global__ void __launch_bounds__(256) sgemm_kernel(
    const float* __restrict__ A, const float* __restrict__ Bm,
    float* __restrict__ C, int M, int N, int Kd)
{
    __shared__ float As[16][65];  // transposed A tile, padded
    __shared__ float Bs[16][64];

    int bm = blockIdx.y * 64, bn = blockIdx.x * 64;
    int tid = threadIdx.x;
    int tx = tid & 15, ty = tid >> 4;

    int am = tid >> 2, ak = (tid & 3) << 2;   // A tile: 64 rows x 16 k
    int bk = tid >> 4, bn4 = (tid & 15) << 2; // B tile: 16 k x 64 cols

    const float* Ap = A + (size_t)(bm + am) * Kd + ak;
    const float* Bp = Bm + (size_t)bk * N + bn + bn4;

    float acc[4][4];
#pragma unroll
    for (int i = 0; i < 4; i++)
#pragma unroll
        for (int j = 0; j < 4; j++) acc[i][j] = 0.f;

    for (int k0 = 0; k0 < Kd; k0 += 16) {
        float4 a4 = *(const float4*)(Ap + k0);
        float4 b4 = *(const float4*)(Bp + (size_t)k0 * N);
        __syncthreads();
        As[ak + 0][am] = a4.x;
        As[ak + 1][am] = a4.y;
        As[ak + 2][am] = a4.z;
        As[ak + 3][am] = a4.w;
        *(float4*)&Bs[bk][bn4] = b4;
        __syncthreads();
#pragma unroll
        for (int kk = 0; kk < 16; ++kk) {
            float a[4], b[4];
#pragma unroll
            for (int i = 0; i < 4; i++) a[i] = As[kk][ty * 4 + i];
            float4 bb = *(const float4*)&Bs[kk][tx * 4];
            b[0] = bb.x; b[1] = bb.y; b[2] = bb.z; b[3] = bb.w;
#pragma unroll
            for (int i = 0; i < 4; i++)
#pragma unroll
                for (int j = 0; j < 4; j++)
                    acc[i][j] = fmaf(a[i], b[j], acc[i][j]);
        }
    }
#pragma unroll
    for (int i = 0; i < 4; i++)
#pragma unroll
        for (int j = 0; j < 4; j++)
            C[(size_t)(bm + ty * 4 + i) * N + bn + tx * 4 + j] = acc[i][j];
}

// ----------------------------------------------------------------------------
// RoPE (in-place): x is (B,T,heads,HD). Half-split rotation, fp32.
// one thread per (b,t,head,freq) pair; freq index i in [0,64).
// ----------------------------------------------------------------------------
__global__ void rope_kernel(float* __restrict__ x, const int* __restrict__ pos,
                            int heads, int total)
{
    int idx = blockIdx.x * blockDim.x + threadIdx.x;
    if (idx >= total) return;
    int i = idx & 63;
    int rem = idx >> 6;
    int h = rem % heads;
    int bt = rem / heads;  // b*T + t

    float p = (float)pos[bt];
    float frac = (float)(2 * i) / 128.f;
    float ts = powf(10000.f, frac);
    float ang = p / ts;
    float s, c;
    sincosf(ang, &s, &c);

    float* base = x + ((size_t)bt * heads + h) * HD;
    float x1 = base[i], x2 = base[i + 64];
    base[i]      = x1 * c - x2 * s;
    base[i + 64] = x2 * c + x1 * s;
}

// ----------------------------------------------------------------------------
// Causal flash attention, fp32, online softmax.
// Block = (qt, n, b); 64 q-rows x 64 kv-cols tiles; 256 threads (16x16).
// Each thread: 4x4 of S, 4x8 of O (rows ty*4.., O cols tx*8..).
// ----------------------------------------------------------------------------
#define FLASH_SMEM_FLOATS (64 * 129 * 2 + 64 * 128 + 64 * 65 + 192)
#define FLASH_SMEM_BYTES (FLASH_SMEM_FLOATS * 4)

__global__ void __launch_bounds__(256) flash_kernel(
    const float* __restrict__ Q, const float* __restrict__ Kg,
    const float* __restrict__ Vg, float* __restrict__ Og)
{
    extern __shared__ float sm[];
    float* Qs = sm;               // 64 x 129 (padded)
    float* Ks = Qs + 64 * 129;    // 64 x 129 (padded)
    float* Vs = Ks + 64 * 129;    // 64 x 128 (float4 reads)
    float* Ss = Vs + 64 * 128;    // 64 x 65
    float* mrow = Ss + 64 * 65;   // 64
    float* lrow = mrow + 64;      // 64
    float* arow = lrow + 64;      // 64

    int qt = blockIdx.x, n = blockIdx.y, b = blockIdx.z;
    int kvh = n >> 2;  // n / G, G=4
    int tid = threadIdx.x;
    int tx = tid & 15, ty = tid >> 4;
    const float scale = 0.08838834764831844f;  // 1/sqrt(128)

    // Load Q tile (64 x 128) into padded smem
    for (int i = tid; i < 64 * 32; i += 256) {
        int r = i >> 5, c = (i & 31) << 2;
        const float* src = Q + (((size_t)(b * T_ + qt * 64 + r)) * NH + n) * HD + c;
        float4 v = *(const float4*)src;
        float* dst = Qs + r * 129 + c;
        dst[0] = v.x; dst[1] = v.y; dst[2] = v.z; dst[3] = v.w;
    }
    if (tid < 64) { mrow[tid] = -1e30f; lrow[tid] = 0.f; }

    float o[4][8];
#pragma unroll
    for (int i = 0; i < 4; i++)
#pragma unroll
        for (int c = 0; c < 8; c++) o[i][c] = 0.f;

    int r0 = ty * 4, c0 = tx * 4, h0 = tx * 8;
    int row = tid >> 2, part = tid & 3;

    for (int kt = 0; kt <= qt; ++kt) {
        __syncthreads();  // previous PV done before overwriting K/V tiles
        for (int i = tid; i < 64 * 32; i += 256) {
            int r = i >> 5, c = (i & 31) << 2;
            size_t gofs = (((size_t)(b * T_ + kt * 64 + r)) * KH + kvh) * HD + c;
            float4 kv = *(const float4*)(Kg + gofs);
            float* kd = Ks + r * 129 + c;
            kd[0] = kv.x; kd[1] = kv.y; kd[2] = kv.z; kd[3] = kv.w;
            float4 vv = *(const float4*)(Vg + gofs);
            *(float4*)(Vs + r * 128 + c) = vv;
        }
        __syncthreads();

        // S = Q K^T (4x4 per thread)
        float s[4][4];
#pragma unroll
        for (int i = 0; i < 4; i++)
#pragma unroll
            for (int j = 0; j < 4; j++) s[i][j] = 0.f;
        for (int kk = 0; kk < HD; ++kk) {
            float a[4], bb[4];
#pragma unroll
            for (int i = 0; i < 4; i++) a[i] = Qs[(r0 + i) * 129 + kk];
#pragma unroll
            for (int j = 0; j < 4; j++) bb[j] = Ks[(c0 + j) * 129 + kk];
#pragma unroll
            for (int i = 0; i < 4; i++)
#pragma unroll
                for (int j = 0; j < 4; j++)
                    s[i][j] = fmaf(a[i], bb[j], s[i][j]);
        }
        bool diag = (kt == qt);
#pragma unroll
        for (int i = 0; i < 4; i++)
#pragma unroll
            for (int j = 0; j < 4; j++) {
                float v = s[i][j] * scale;
                if (diag && (c0 + j > r0 + i)) v = -1e30f;
                Ss[(r0 + i) * 65 + c0 + j] = v;
            }
        __syncthreads();

        // Online softmax: 4 threads per row
        float mx = -1e30f;
#pragma unroll
        for (int c = 0; c < 16; ++c)
            mx = fmaxf(mx, Ss[row * 65 + part * 16 + c]);
        mx = fmaxf(mx, __shfl_xor_sync(0xffffffffu, mx, 1));
        mx = fmaxf(mx, __shfl_xor_sync(0xffffffffu, mx, 2));
        float m_old = mrow[row];
        float m_new = fmaxf(m_old, mx);
        float sum = 0.f;
#pragma unroll
        for (int c = 0; c < 16; ++c) {
            float p = __expf(Ss[row * 65 + part * 16 + c] - m_new);
            Ss[row * 65 + part * 16 + c] = p;
            sum += p;
        }
        sum += __shfl_xor_sync(0xffffffffu, sum, 1);
        sum += __shfl_xor_sync(0xffffffffu, sum, 2);
        if (part == 0) {
            float alpha = __expf(m_old - m_new);
            arow[row] = alpha;
            mrow[row] = m_new;
            lrow[row] = lrow[row] * alpha + sum;
        }
        __syncthreads();

        // Rescale O, accumulate P @ V
        float al[4];
#pragma unroll
        for (int i = 0; i < 4; i++) al[i] = arow[r0 + i];
#pragma unroll
        for (int i = 0; i < 4; i++)
#pragma unroll
            for (int c = 0; c < 8; c++) o[i][c] *= al[i];

        for (int j = 0; j < 64; ++j) {
            float4 v0 = *(const float4*)(Vs + j * 128 + h0);
            float4 v1 = *(const float4*)(Vs + j * 128 + h0 + 4);
            float p_[4];
#pragma unroll
            for (int i = 0; i < 4; i++) p_[i] = Ss[(r0 + i) * 65 + j];
#pragma unroll
            for (int i = 0; i < 4; i++) {
                o[i][0] = fmaf(p_[i], v0.x, o[i][0]);
                o[i][1] = fmaf(p_[i], v0.y, o[i][1]);
                o[i][2] = fmaf(p_[i], v0.z, o[i][2]);
                o[i][3] = fmaf(p_[i], v0.w, o[i][3]);
                o[i][4] = fmaf(p_[i], v1.x, o[i][4]);
                o[i][5] = fmaf(p_[i], v1.y, o[i][5]);
                o[i][6] = fmaf(p_[i], v1.z, o[i][6]);
                o[i][7] = fmaf(p_[i], v1.w, o[i][7]);
            }
        }
    }

    // Normalize and write attn (B,T,N,H)
#pragma unroll
    for (int i = 0; i < 4; i++) {
        float linv = 1.f / lrow[r0 + i];
        float* dst = Og + (((size_t)(b * T_ + qt * 64 + r0 + i)) * NH + n) * HD + h0;
#pragma unroll
        for (int c = 0; c < 8; c++) dst[c] = o[i][c] * linv;
    }
}

// ----------------------------------------------------------------------------
// Launch
// ----------------------------------------------------------------------------
extern "C" void kernel_launch(void* const* d_in, const int* in_sizes, int n_in,
                              void* d_out, int out_size)
{
    const float* Xq  = (const float*)d_in[0];
    const float* Xkv = (const float*)d_in[1];
    const int* qpos  = (const int*)d_in[2];
    const int* kvpos = (const int*)d_in[3];
    const float* Wq  = (const float*)d_in[4];
    const float* Wk  = (const float*)d_in[5];
    const float* Wv  = (const float*)d_in[6];
    const float* Wo  = (const float*)d_in[7];
    float* out = (float*)d_out;

    float *pQ, *pK, *pV, *pA;
    cudaGetSymbolAddress((void**)&pQ, g_Q);
    cudaGetSymbolAddress((void**)&pK, g_K);
    cudaGetSymbolAddress((void**)&pV, g_V);
    cudaGetSymbolAddress((void**)&pA, g_attn);

    cudaFuncSetAttribute(flash_kernel,
                         cudaFuncAttributeMaxDynamicSharedMemorySize,
                         FLASH_SMEM_BYTES);

    dim3 blk(256);
    int M = B_ * T_;  // 4096

    // Projections
    sgemm_kernel<<<dim3((NH * HD) / 64, M / 64), blk>>>(Xq, Wq, pQ, M, NH * HD, D_);
    sgemm_kernel<<<dim3((KH * HD) / 64, M / 64), blk>>>(Xkv, Wk, pK, M, KH * HD, D_);
    sgemm_kernel<<<dim3((KH * HD) / 64, M / 64), blk>>>(Xkv, Wv, pV, M, KH * HD, D_);

    // RoPE
    int totQ = B_ * T_ * NH * 64;
    rope_kernel<<<(totQ + 255) / 256, 256>>>(pQ, qpos, NH, totQ);
    int totK = B_ * T_ * KH * 64;
    rope_kernel<<<(totK + 255) / 256, 256>>>(pK, kvpos, KH, totK);

    // Causal flash attention
    flash_kernel<<<dim3(T_ / 64, NH, B_), blk, FLASH_SMEM_BYTES>>>(pQ, pK, pV, pA);

    // Output projection
    sgemm_kernel<<<dim3(D_ / 64, M / 64), blk>>>(pA, Wo, out, M, D_, NH * HD);
}

// round 3
// speedup vs baseline: 1.2797x; 1.2797x over previous
#include <cuda_runtime.h>
#include <math.h>
#include <stdint.h>

#define B_ 2
#define T_ 2048
#define D_ 2048
#define NH 16
#define KH 4
#define HD 128

// Scratch (static device globals — no allocation allowed)
__device__ float g_Q[(size_t)B_ * T_ * NH * HD];     // (B,T,N,H)
__device__ float g_K[(size_t)B_ * T_ * KH * HD];     // (B,T,K,H)
__device__ float g_V[(size_t)B_ * T_ * KH * HD];     // (B,T,K,H)
__device__ float g_attn[(size_t)B_ * T_ * NH * HD];  // (B,T,N,H)

// ----------------------------------------------------------------------------
// 3xTF32 tensor-core GEMM: C[M,N] = A[M,Kd] * B[Kd,N], row-major fp32 in/out.
// Each operand split hi/lo; acc += hi*hi + hi*lo + lo*hi  (fp32-accurate).
// 128x128 block tile, BK=16, 256 threads (8 warps, 4x2), warp tile 32x64.
// ----------------------------------------------------------------------------
#define SA 20   // smem A row stride (floats): banks (20r+c)%32 distinct
#define SB 136  // smem B row stride (floats): banks (8k+c)%32 distinct

__device__ __forceinline__ void cp16(uint32_t dst, const void* src) {
    asm volatile("cp.async.ca.shared.global [%0], [%1], 16;\n" ::"r"(dst), "l"(src));
}

__device__ __forceinline__ void split_tf32(float f, uint32_t& hi, uint32_t& lo) {
    uint32_t h;
    asm("cvt.rna.tf32.f32 %0, %1;" : "=r"(h) : "f"(f));
    float lf = f - __uint_as_float(h);
    uint32_t l;
    asm("cvt.rna.tf32.f32 %0, %1;" : "=r"(l) : "f"(lf));
    hi = h; lo = l;
}

__device__ __forceinline__ void mma_tf32(float* d, const uint32_t* a, const uint32_t* b) {
    asm volatile(
        "mma.sync.aligned.m16n8k8.row.col.f32.tf32.tf32.f32 "
        "{%0,%1,%2,%3}, {%4,%5,%6,%7}, {%8,%9}, {%0,%1,%2,%3};\n"
        : "+f"(d[0]), "+f"(d[1]), "+f"(d[2]), "+f"(d[3])
        : "r"(a[0]), "r"(a[1]), "r"(a[2]), "r"(a[3]), "r"(b[0]), "r"(b[1]));
}

__global__ void __launch_bounds__(256) tf32_gemm_kernel(
    const float* __restrict__ A, const float* __restrict__ Bm,
    float* __restrict__ C, int M, int N, int Kd)
{
    __shared__ float smA[2][128 * SA];
    __shared__ float smB[2][16 * SB];

    int bm = blockIdx.y * 128, bn = blockIdx.x * 128;
    int tid = threadIdx.x;
    int warp = tid >> 5, lane = tid & 31;
    int wm = warp & 3, wn = warp >> 2;
    int m0 = wm * 32, n0 = wn * 64;

    uint32_t smA_u[2], smB_u[2];
    smA_u[0] = (uint32_t)__cvta_generic_to_shared(&smA[0][0]);
    smA_u[1] = (uint32_t)__cvta_generic_to_shared(&smA[1][0]);
    smB_u[0] = (uint32_t)__cvta_generic_to_shared(&smB[0][0]);
    smB_u[1] = (uint32_t)__cvta_generic_to_shared(&smB[1][0]);

    float acc[2][8][4];
#pragma unroll
    for (int mt = 0; mt < 2; mt++)
#pragma unroll
        for (int nt = 0; nt < 8; nt++)
#pragma unroll
            for (int r = 0; r < 4; r++) acc[mt][nt][r] = 0.f;

    int nK = Kd >> 4;

    auto load_stage = [&](int stage, int k0) {
#pragma unroll
        for (int c = tid; c < 512; c += 256) {
            int row = c >> 2, seg = (c & 3) << 2;
            const float* src = A + (size_t)(bm + row) * Kd + k0 + seg;
            cp16(smA_u[stage] + (uint32_t)(row * SA + seg) * 4u, src);
        }
#pragma unroll
        for (int c = tid; c < 512; c += 256) {
            int row = c >> 5, seg = (c & 31) << 2;
            const float* src = Bm + (size_t)(k0 + row) * N + bn + seg;
            cp16(smB_u[stage] + (uint32_t)(row * SB + seg) * 4u, src);
        }
        asm volatile("cp.async.commit_group;\n" ::);
    };

    load_stage(0, 0);

    int ar = lane >> 2, ac = lane & 3;  // A frag row/col within 16x8
    int br = lane & 3, bc = lane >> 2;  // B frag k/col within 8x8

    for (int kc = 0; kc < nK; kc++) {
        int stage = kc & 1;
        if (kc + 1 < nK) {
            load_stage(stage ^ 1, (kc + 1) << 4);
            asm volatile("cp.async.wait_group 1;\n" ::);
        } else {
            asm volatile("cp.async.wait_group 0;\n" ::);
        }
        __syncthreads();

        const float* As = smA[stage];
        const float* Bs = smB[stage];

#pragma unroll
        for (int ks = 0; ks < 2; ks++) {
            uint32_t ah[2][4], al_[2][4], bh[8][2], bl[8][2];
#pragma unroll
            for (int mt = 0; mt < 2; mt++) {
                int base = (m0 + mt * 16 + ar) * SA + ks * 8 + ac;
                split_tf32(As[base],              ah[mt][0], al_[mt][0]);
                split_tf32(As[base + 8 * SA],     ah[mt][1], al_[mt][1]);
                split_tf32(As[base + 4],          ah[mt][2], al_[mt][2]);
                split_tf32(As[base + 8 * SA + 4], ah[mt][3], al_[mt][3]);
            }
#pragma unroll
            for (int nt = 0; nt < 8; nt++) {
                int idx = (ks * 8 + br) * SB + n0 + nt * 8 + bc;
                split_tf32(Bs[idx],          bh[nt][0], bl[nt][0]);
                split_tf32(Bs[idx + 4 * SB], bh[nt][1], bl[nt][1]);
            }
#pragma unroll
            for (int mt = 0; mt < 2; mt++)
#pragma unroll
                for (int nt = 0; nt < 8; nt++) {
                    mma_tf32(acc[mt][nt], al_[mt], bh[nt]);  // lo*hi
                    mma_tf32(acc[mt][nt], ah[mt], bl[nt]);   // hi*lo
                    mma_tf32(acc[mt][nt], ah[mt], bh[nt]);   // hi*hi
                }
        }
        __syncthreads();
    }

#pragma unroll
    for (int mt = 0; mt < 2; mt++) {
        int row = bm + m0 + mt * 16 + (lane >> 2);
#pragma unroll
        for (int nt = 0; nt < 8; nt++) {
            int col = bn + n0 + nt * 8 + ((lane & 3) << 1);
            float2 v0 = make_float2(acc[mt][nt][0], acc[mt][nt][1]);
            float2 v1 = make_float2(acc[mt][nt][2], acc[mt][nt][3]);
            *(float2*)(C + (size_t)row * N + col) = v0;
            *(float2*)(C + (size_t)(row + 8) * N + col) = v1;
        }
    }
}

// ----------------------------------------------------------------------------
// RoPE (in-place): x is (B,T,heads,HD). Half-split rotation, fp32.
// ----------------------------------------------------------------------------
__global__ void rope_kernel(float* __restrict__ x, const int* __restrict__ pos,
                            int heads, int total)
{
    int idx = blockIdx.x * blockDim.x + threadIdx.x;
    if (idx >= total) return;
    int i = idx & 63;
    int rem = idx >> 6;
    int h = rem % heads;
    int bt = rem / heads;  // b*T + t

    float p = (float)pos[bt];
    float frac = (float)(2 * i) / 128.f;
    float ts = powf(10000.f, frac);
    float ang = p / ts;
    float s, c;
    sincosf(ang, &s, &c);

    float* base = x + ((size_t)bt * heads + h) * HD;
    float x1 = base[i], x2 = base[i + 64];
    base[i]      = x1 * c - x2 * s;
    base[i + 64] = x2 * c + x1 * s;
}

// ----------------------------------------------------------------------------
// Causal flash attention, fp32, online softmax (unchanged — correct in R1).
// ----------------------------------------------------------------------------
#define FLASH_SMEM_FLOATS (64 * 129 * 2 + 64 * 128 + 64 * 65 + 192)
#define FLASH_SMEM_BYTES (FLASH_SMEM_FLOATS * 4)

__global__ void __launch_bounds__(256) flash_kernel(
    const float* __restrict__ Q, const float* __restrict__ Kg,
    const float* __restrict__ Vg, float* __restrict__ Og)
{
    extern __shared__ float sm[];
    float* Qs = sm;               // 64 x 129 (padded)
    float* Ks = Qs + 64 * 129;    // 64 x 129 (padded)
    float* Vs = Ks + 64 * 129;    // 64 x 128 (float4 reads)
    float* Ss = Vs + 64 * 128;    // 64 x 65
    float* mrow = Ss + 64 * 65;   // 64
    float* lrow = mrow + 64;      // 64
    float* arow = lrow + 64;      // 64

    int qt = blockIdx.x, n = blockIdx.y, b = blockIdx.z;
    int kvh = n >> 2;  // n / G, G=4
    int tid = threadIdx.x;
    int tx = tid & 15, ty = tid >> 4;
    const float scale = 0.08838834764831844f;  // 1/sqrt(128)

    for (int i = tid; i < 64 * 32; i += 256) {
        int r = i >> 5, c = (i & 31) << 2;
        const float* src = Q + (((size_t)(b * T_ + qt * 64 + r)) * NH + n) * HD + c;
        float4 v = *(const float4*)src;
        float* dst = Qs + r * 129 + c;
        dst[0] = v.x; dst[1] = v.y; dst[2] = v.z; dst[3] = v.w;
    }
    if (tid < 64) { mrow[tid] = -1e30f; lrow[tid] = 0.f; }

    float o[4][8];
#pragma unroll
    for (int i = 0; i < 4; i++)
#pragma unroll
        for (int c = 0; c < 8; c++) o[i][c] = 0.f;

    int r0 = ty * 4, c0 = tx * 4, h0 = tx * 8;
    int row = tid >> 2, part = tid & 3;

    for (int kt = 0; kt <= qt; ++kt) {
        __syncthreads();
        for (int i = tid; i < 64 * 32; i += 256) {
            int r = i >> 5, c = (i & 31) << 2;
            size_t gofs = (((size_t)(b * T_ + kt * 64 + r)) * KH + kvh) * HD + c;
            float4 kv = *(const float4*)(Kg + gofs);
            float* kd = Ks + r * 129 + c;
            kd[0] = kv.x; kd[1] = kv.y; kd[2] = kv.z; kd[3] = kv.w;
            float4 vv = *(const float4*)(Vg + gofs);
            *(float4*)(Vs + r * 128 + c) = vv;
        }
        __syncthreads();

        float s[4][4];
#pragma unroll
        for (int i = 0; i < 4; i++)
#pragma unroll
            for (int j = 0; j < 4; j++) s[i][j] = 0.f;
        for (int kk = 0; kk < HD; ++kk) {
            float a[4], bb[4];
#pragma unroll
            for (int i = 0; i < 4; i++) a[i] = Qs[(r0 + i) * 129 + kk];
#pragma unroll
            for (int j = 0; j < 4; j++) bb[j] = Ks[(c0 + j) * 129 + kk];
#pragma unroll
            for (int i = 0; i < 4; i++)
#pragma unroll
                for (int j = 0; j < 4; j++)
                    s[i][j] = fmaf(a[i], bb[j], s[i][j]);
        }
        bool diag = (kt == qt);
#pragma unroll
        for (int i = 0; i < 4; i++)
#pragma unroll
            for (int j = 0; j < 4; j++) {
                float v = s[i][j] * scale;
                if (diag && (c0 + j > r0 + i)) v = -1e30f;
                Ss[(r0 + i) * 65 + c0 + j] = v;
            }
        __syncthreads();

        float mx = -1e30f;
#pragma unroll
        for (int c = 0; c < 16; ++c)
            mx = fmaxf(mx, Ss[row * 65 + part * 16 + c]);
        mx = fmaxf(mx, __shfl_xor_sync(0xffffffffu, mx, 1));
        mx = fmaxf(mx, __shfl_xor_sync(0xffffffffu, mx, 2));
        float m_old = mrow[row];
        float m_new = fmaxf(m_old, mx);
        float sum = 0.f;
#pragma unroll
        for (int c = 0; c < 16; ++c) {
            float p = __expf(Ss[row * 65 + part * 16 + c] - m_new);
            Ss[row * 65 + part * 16 + c] = p;
            sum += p;
        }
        sum += __shfl_xor_sync(0xffffffffu, sum, 1);
        sum += __shfl_xor_sync(0xffffffffu, sum, 2);
        if (part == 0) {
            float alpha = __expf(m_old - m_new);
            arow[row] = alpha;
            mrow[row] = m_new;
            lrow[row] = lrow[row] * alpha + sum;
        }
        __syncthreads();

        float al[4];
#pragma unroll
        for (int i = 0; i < 4; i++) al[i] = arow[r0 + i];
#pragma unroll
        for (int i = 0; i < 4; i++)
#pragma unroll
            for (int c = 0; c < 8; c++) o[i][c] *= al[i];

        for (int j = 0; j < 64; ++j) {
            float4 v0 = *(const float4*)(Vs + j * 128 + h0);
            float4 v1 = *(const float4*)(Vs + j * 128 + h0 + 4);
            float p_[4];
#pragma unroll
            for (int i = 0; i < 4; i++) p_[i] = Ss[(r0 + i) * 65 + j];
#pragma unroll
            for (int i = 0; i < 4; i++) {
                o[i][0] = fmaf(p_[i], v0.x, o[i][0]);
                o[i][1] = fmaf(p_[i], v0.y, o[i][1]);
                o[i][2] = fmaf(p_[i], v0.z, o[i][2]);
                o[i][3] = fmaf(p_[i], v0.w, o[i][3]);
                o[i][4] = fmaf(p_[i], v1.x, o[i][4]);
                o[i][5] = fmaf(p_[i], v1.y, o[i][5]);
                o[i][6] = fmaf(p_[i], v1.z, o[i][6]);
                o[i][7] = fmaf(p_[i], v1.w, o[i][7]);
            }
        }
    }

#pragma unroll
    for (int i = 0; i < 4; i++) {
        float linv = 1.f / lrow[r0 + i];
        float* dst = Og + (((size_t)(b * T_ + qt * 64 + r0 + i)) * NH + n) * HD + h0;
#pragma unroll
        for (int c = 0; c < 8; c++) dst[c] = o[i][c] * linv;
    }
}

// ----------------------------------------------------------------------------
// Launch
// ----------------------------------------------------------------------------
extern "C" void kernel_launch(void* const* d_in, const int* in_sizes, int n_in,
                              void* d_out, int out_size)
{
    const float* Xq  = (const float*)d_in[0];
    const float* Xkv = (const float*)d_in[1];
    const int* qpos  = (const int*)d_in[2];
    const int* kvpos = (const int*)d_in[3];
    const float* Wq  = (const float*)d_in[4];
    const float* Wk  = (const float*)d_in[5];
    const float* Wv  = (const float*)d_in[6];
    const float* Wo  = (const float*)d_in[7];
    float* out = (float*)d_out;

    float *pQ, *pK, *pV, *pA;
    cudaGetSymbolAddress((void**)&pQ, g_Q);
    cudaGetSymbolAddress((void**)&pK, g_K);
    cudaGetSymbolAddress((void**)&pV, g_V);
    cudaGetSymbolAddress((void**)&pA, g_attn);

    cudaFuncSetAttribute(flash_kernel,
                         cudaFuncAttributeMaxDynamicSharedMemorySize,
                         FLASH_SMEM_BYTES);

    int M = B_ * T_;  // 4096

    // Projections (3xTF32 tensor cores, fp32-accurate)
    tf32_gemm_kernel<<<dim3((NH * HD) / 128, M / 128), 256>>>(Xq, Wq, pQ, M, NH * HD, D_);
    tf32_gemm_kernel<<<dim3((KH * HD) / 128, M / 128), 256>>>(Xkv, Wk, pK, M, KH * HD, D_);
    tf32_gemm_kernel<<<dim3((KH * HD) / 128, M / 128), 256>>>(Xkv, Wv, pV, M, KH * HD, D_);

    // RoPE
    int totQ = B_ * T_ * NH * 64;
    rope_kernel<<<(totQ + 255) / 256, 256>>>(pQ, qpos, NH, totQ);
    int totK = B_ * T_ * KH * 64;
    rope_kernel<<<(totK + 255) / 256, 256>>>(pK, kvpos, KH, totK);

    // Causal flash attention (fp32)
    flash_kernel<<<dim3(T_ / 64, NH, B_), 256, FLASH_SMEM_BYTES>>>(pQ, pK, pV, pA);

    // Output projection (3xTF32 tensor cores)
    tf32_gemm_kernel<<<dim3(D_ / 128, M / 128), 256>>>(pA, Wo, out, M, D_, NH * HD);
}

// round 5
// speedup vs baseline: 1.7862x; 1.3958x over previous
#include <cuda_runtime.h>
#include <cuda_bf16.h>
#include <math.h>
#include <stdint.h>

#define B_ 2
#define T_ 2048
#define D_ 2048
#define NH 16
#define KH 4
#define HD 128

// Scratch (static device globals — no allocation allowed)
__device__ float g_Q[(size_t)B_ * T_ * NH * HD];     // (B,T,N,H)
__device__ float g_K[(size_t)B_ * T_ * KH * HD];     // (B,T,K,H)
__device__ float g_V[(size_t)B_ * T_ * KH * HD];     // (B,T,K,H)
__device__ float g_attn[(size_t)B_ * T_ * NH * HD];  // (B,T,N,H)

// ============================================================================
// Helpers
// ============================================================================
__device__ __forceinline__ void cp16(uint32_t dst, const void* src) {
    asm volatile("cp.async.ca.shared.global [%0], [%1], 16;\n" ::"r"(dst), "l"(src));
}

// Split (a,b) into hi/lo bf16x2 words: hi.x=bf16(a), hi.y=bf16(b); lo = residual.
__device__ __forceinline__ void split_pair(float a, float b, uint32_t& hi, uint32_t& lo) {
    __nv_bfloat16 ha = __float2bfloat16_rn(a);
    __nv_bfloat16 hb = __float2bfloat16_rn(b);
    float ra = a - __bfloat162float(ha);
    float rb = b - __bfloat162float(hb);
    __nv_bfloat162 h2;
    h2.x = ha; h2.y = hb;
    __nv_bfloat162 l2 = __floats2bfloat162_rn(ra, rb);
    hi = *reinterpret_cast<uint32_t*>(&h2);
    lo = *reinterpret_cast<uint32_t*>(&l2);
}

__device__ __forceinline__ void mma_bf16(float* d, const uint32_t* a, const uint32_t* b) {
    asm volatile(
        "mma.sync.aligned.m16n8k16.row.col.f32.bf16.bf16.f32 "
        "{%0,%1,%2,%3}, {%4,%5,%6,%7}, {%8,%9}, {%0,%1,%2,%3};\n"
        : "+f"(d[0]), "+f"(d[1]), "+f"(d[2]), "+f"(d[3])
        : "r"(a[0]), "r"(a[1]), "r"(a[2]), "r"(a[3]), "r"(b[0]), "r"(b[1]));
}

__device__ __forceinline__ void split_tf32(float f, uint32_t& hi, uint32_t& lo) {
    uint32_t h;
    asm("cvt.rna.tf32.f32 %0, %1;" : "=r"(h) : "f"(f));
    float lf = f - __uint_as_float(h);
    uint32_t l;
    asm("cvt.rna.tf32.f32 %0, %1;" : "=r"(l) : "f"(lf));
    hi = h; lo = l;
}

__device__ __forceinline__ void mma_tf32(float* d, const uint32_t* a, const uint32_t* b) {
    asm volatile(
        "mma.sync.aligned.m16n8k8.row.col.f32.tf32.tf32.f32 "
        "{%0,%1,%2,%3}, {%4,%5,%6,%7}, {%8,%9}, {%0,%1,%2,%3};\n"
        : "+f"(d[0]), "+f"(d[1]), "+f"(d[2]), "+f"(d[3])
        : "r"(a[0]), "r"(a[1]), "r"(a[2]), "r"(a[3]), "r"(b[0]), "r"(b[1]));
}

// ============================================================================
// 3xTF32 GEMM (unchanged from R3 — passing). C = A * B, row-major fp32.
// ============================================================================
#define SA 20
#define SB 136

__global__ void __launch_bounds__(256) tf32_gemm_kernel(
    const float* __restrict__ A, const float* __restrict__ Bm,
    float* __restrict__ C, int M, int N, int Kd)
{
    __shared__ float smA[2][128 * SA];
    __shared__ float smB[2][16 * SB];

    int bm = blockIdx.y * 128, bn = blockIdx.x * 128;
    int tid = threadIdx.x;
    int warp = tid >> 5, lane = tid & 31;
    int wm = warp & 3, wn = warp >> 2;
    int m0 = wm * 32, n0 = wn * 64;

    uint32_t smA_u[2], smB_u[2];
    smA_u[0] = (uint32_t)__cvta_generic_to_shared(&smA[0][0]);
    smA_u[1] = (uint32_t)__cvta_generic_to_shared(&smA[1][0]);
    smB_u[0] = (uint32_t)__cvta_generic_to_shared(&smB[0][0]);
    smB_u[1] = (uint32_t)__cvta_generic_to_shared(&smB[1][0]);

    float acc[2][8][4];
#pragma unroll
    for (int mt = 0; mt < 2; mt++)
#pragma unroll
        for (int nt = 0; nt < 8; nt++)
#pragma unroll
            for (int r = 0; r < 4; r++) acc[mt][nt][r] = 0.f;

    int nK = Kd >> 4;

    auto load_stage = [&](int stage, int k0) {
#pragma unroll
        for (int c = tid; c < 512; c += 256) {
            int row = c >> 2, seg = (c & 3) << 2;
            const float* src = A + (size_t)(bm + row) * Kd + k0 + seg;
            cp16(smA_u[stage] + (uint32_t)(row * SA + seg) * 4u, src);
        }
#pragma unroll
        for (int c = tid; c < 512; c += 256) {
            int row = c >> 5, seg = (c & 31) << 2;
            const float* src = Bm + (size_t)(k0 + row) * N + bn + seg;
            cp16(smB_u[stage] + (uint32_t)(row * SB + seg) * 4u, src);
        }
        asm volatile("cp.async.commit_group;\n" ::);
    };

    load_stage(0, 0);

    int ar = lane >> 2, ac = lane & 3;
    int br = lane & 3, bc = lane >> 2;

    for (int kc = 0; kc < nK; kc++) {
        int stage = kc & 1;
        if (kc + 1 < nK) {
            load_stage(stage ^ 1, (kc + 1) << 4);
            asm volatile("cp.async.wait_group 1;\n" ::);
        } else {
            asm volatile("cp.async.wait_group 0;\n" ::);
        }
        __syncthreads();

        const float* As = smA[stage];
        const float* Bs = smB[stage];

#pragma unroll
        for (int ks = 0; ks < 2; ks++) {
            uint32_t ah[2][4], al_[2][4], bh[8][2], bl[8][2];
#pragma unroll
            for (int mt = 0; mt < 2; mt++) {
                int base = (m0 + mt * 16 + ar) * SA + ks * 8 + ac;
                split_tf32(As[base],              ah[mt][0], al_[mt][0]);
                split_tf32(As[base + 8 * SA],     ah[mt][1], al_[mt][1]);
                split_tf32(As[base + 4],          ah[mt][2], al_[mt][2]);
                split_tf32(As[base + 8 * SA + 4], ah[mt][3], al_[mt][3]);
            }
#pragma unroll
            for (int nt = 0; nt < 8; nt++) {
                int idx = (ks * 8 + br) * SB + n0 + nt * 8 + bc;
                split_tf32(Bs[idx],          bh[nt][0], bl[nt][0]);
                split_tf32(Bs[idx + 4 * SB], bh[nt][1], bl[nt][1]);
            }
#pragma unroll
            for (int mt = 0; mt < 2; mt++)
#pragma unroll
                for (int nt = 0; nt < 8; nt++) {
                    mma_tf32(acc[mt][nt], al_[mt], bh[nt]);
                    mma_tf32(acc[mt][nt], ah[mt], bl[nt]);
                    mma_tf32(acc[mt][nt], ah[mt], bh[nt]);
                }
        }
        __syncthreads();
    }

#pragma unroll
    for (int mt = 0; mt < 2; mt++) {
        int row = bm + m0 + mt * 16 + (lane >> 2);
#pragma unroll
        for (int nt = 0; nt < 8; nt++) {
            int col = bn + n0 + nt * 8 + ((lane & 3) << 1);
            float2 v0 = make_float2(acc[mt][nt][0], acc[mt][nt][1]);
            float2 v1 = make_float2(acc[mt][nt][2], acc[mt][nt][3]);
            *(float2*)(C + (size_t)row * N + col) = v0;
            *(float2*)(C + (size_t)(row + 8) * N + col) = v1;
        }
    }
}

// ============================================================================
// RoPE (unchanged)
// ============================================================================
__global__ void rope_kernel(float* __restrict__ x, const int* __restrict__ pos,
                            int heads, int total)
{
    int idx = blockIdx.x * blockDim.x + threadIdx.x;
    if (idx >= total) return;
    int i = idx & 63;
    int rem = idx >> 6;
    int h = rem % heads;
    int bt = rem / heads;

    float p = (float)pos[bt];
    float frac = (float)(2 * i) / 128.f;
    float ts = powf(10000.f, frac);
    float ang = p / ts;
    float s, c;
    sincosf(ang, &s, &c);

    float* base = x + ((size_t)bt * heads + h) * HD;
    float x1 = base[i], x2 = base[i + 64];
    base[i]      = x1 * c - x2 * s;
    base[i + 64] = x2 * c + x1 * s;
}

// ============================================================================
// Tensor-core causal flash attention (bf16 hi/lo 3-product MMA).
// Block: 64 q-rows x 64 kv per iter, 256 threads = 8 warps.
// QK^T: warp(wq,wc) computes S rows [16wq,16wq+16) x cols [32wc,32wc+32).
// PV:   warp(wq,wc) computes O rows [16wq,16wq+16) x H cols [64wc,64wc+64).
// Smem words (uint32): QsH/QsL 64x68, KsH/KsL 64x68, VsH/VsL 32x132,
// Ss fp32 64x66, m/l/a rows 3x64.  Total = 30272 words = 121,088 B.
// ============================================================================
#define QS_STRIDE 68
#define VS_STRIDE 132
#define SS_STRIDE 66
#define FLASH_SMEM_BYTES ((4 * 64 * QS_STRIDE + 2 * 32 * VS_STRIDE + 64 * SS_STRIDE + 192) * 4)

__global__ void __launch_bounds__(256) flash_kernel(
    const float* __restrict__ Q, const float* __restrict__ Kg,
    const float* __restrict__ Vg, float* __restrict__ Og)
{
    extern __shared__ uint32_t smw[];
    uint32_t* QsH = smw;
    uint32_t* QsL = QsH + 64 * QS_STRIDE;
    uint32_t* KsH = QsL + 64 * QS_STRIDE;
    uint32_t* KsL = KsH + 64 * QS_STRIDE;
    uint32_t* VsH = KsL + 64 * QS_STRIDE;
    uint32_t* VsL = VsH + 32 * VS_STRIDE;
    float* Ss   = (float*)(VsL + 32 * VS_STRIDE);
    float* mrow = Ss + 64 * SS_STRIDE;
    float* lrow = mrow + 64;
    float* arow = lrow + 64;

    int qt = blockIdx.x, n = blockIdx.y, b = blockIdx.z;
    int kvh = n >> 2;
    int tid = threadIdx.x, lane = tid & 31, warp = tid >> 5;
    int wq = warp & 3, wc = warp >> 2;
    int lr = lane >> 2, lc = lane & 3;
    const float scale = 0.08838834764831844f;  // 1/sqrt(128)

    int r0 = wq * 16;        // warp q-row strip
    int n0 = wc * 32;        // warp S col strip
    int h0c = wc * 64;       // warp O col strip

    // --- Load Q tile (64 x 128) -> hi/lo bf16x2 words ---
    for (int i = tid; i < 64 * 32; i += 256) {
        int r = i >> 5, c4 = (i & 31) << 2;
        const float* src = Q + (((size_t)(b * T_ + qt * 64 + r)) * NH + n) * HD + c4;
        float4 v = *(const float4*)src;
        uint32_t h0, l0, h1, l1;
        split_pair(v.x, v.y, h0, l0);
        split_pair(v.z, v.w, h1, l1);
        int p = c4 >> 1;
        QsH[r * QS_STRIDE + p] = h0; QsH[r * QS_STRIDE + p + 1] = h1;
        QsL[r * QS_STRIDE + p] = l0; QsL[r * QS_STRIDE + p + 1] = l1;
    }
    if (tid < 64) { mrow[tid] = -1e30f; lrow[tid] = 0.f; }

    float o[8][4];
#pragma unroll
    for (int nt = 0; nt < 8; nt++)
#pragma unroll
        for (int r = 0; r < 4; r++) o[nt][r] = 0.f;

    int row = tid >> 2, part = tid & 3;  // softmax roles

    for (int kt = 0; kt <= qt; ++kt) {
        __syncthreads();  // prior PV reads of Vs/Ss done

        // --- Load K tile (64 x 128) ---
        for (int i = tid; i < 64 * 32; i += 256) {
            int r = i >> 5, c4 = (i & 31) << 2;
            size_t g = (((size_t)(b * T_ + kt * 64 + r)) * KH + kvh) * HD + c4;
            float4 v = *(const float4*)(Kg + g);
            uint32_t h0, l0, h1, l1;
            split_pair(v.x, v.y, h0, l0);
            split_pair(v.z, v.w, h1, l1);
            int p = c4 >> 1;
            KsH[r * QS_STRIDE + p] = h0; KsH[r * QS_STRIDE + p + 1] = h1;
            KsL[r * QS_STRIDE + p] = l0; KsL[r * QS_STRIDE + p + 1] = l1;
        }
        // --- Load V tile (64 x 128), paired along kv: word(kp,h)={V[2kp][h],V[2kp+1][h]} ---
        for (int i = tid; i < 32 * 32; i += 256) {
            int kp = i >> 5, h4 = (i & 31) << 2;
            size_t g0 = (((size_t)(b * T_ + kt * 64 + 2 * kp)) * KH + kvh) * HD + h4;
            size_t g1 = g0 + (size_t)KH * HD;
            float4 va = *(const float4*)(Vg + g0);
            float4 vb = *(const float4*)(Vg + g1);
            float av[4] = {va.x, va.y, va.z, va.w};
            float bv[4] = {vb.x, vb.y, vb.z, vb.w};
#pragma unroll
            for (int j = 0; j < 4; j++) {
                uint32_t hh, ll;
                split_pair(av[j], bv[j], hh, ll);
                VsH[kp * VS_STRIDE + h4 + j] = hh;
                VsL[kp * VS_STRIDE + h4 + j] = ll;
            }
        }
        __syncthreads();

        // --- S = Q K^T via bf16 MMA (3 products) ---
        float s[4][4];
#pragma unroll
        for (int nt = 0; nt < 4; nt++)
#pragma unroll
            for (int r = 0; r < 4; r++) s[nt][r] = 0.f;

#pragma unroll
        for (int kc = 0; kc < 8; kc++) {
            int pa = 8 * kc + lc;
            int ra = (r0 + lr) * QS_STRIDE, rb = (r0 + 8 + lr) * QS_STRIDE;
            uint32_t aH[4], aL[4];
            aH[0] = QsH[ra + pa];     aH[1] = QsH[rb + pa];
            aH[2] = QsH[ra + pa + 4]; aH[3] = QsH[rb + pa + 4];
            aL[0] = QsL[ra + pa];     aL[1] = QsL[rb + pa];
            aL[2] = QsL[ra + pa + 4]; aL[3] = QsL[rb + pa + 4];
#pragma unroll
            for (int nt = 0; nt < 4; nt++) {
                int nn = (n0 + nt * 8 + lr) * QS_STRIDE;
                uint32_t bH[2] = {KsH[nn + pa], KsH[nn + pa + 4]};
                uint32_t bL[2] = {KsL[nn + pa], KsL[nn + pa + 4]};
                mma_bf16(s[nt], aH, bH);
                mma_bf16(s[nt], aH, bL);
                mma_bf16(s[nt], aL, bH);
            }
        }

        // scale + causal mask + store to Ss
        bool diag = (kt == qt);
        int rq0 = r0 + lr, rq1 = r0 + 8 + lr;
#pragma unroll
        for (int nt = 0; nt < 4; nt++) {
            int col = n0 + nt * 8 + (lc << 1);
            float v0 = s[nt][0] * scale, v1 = s[nt][1] * scale;
            float v2 = s[nt][2] * scale, v3 = s[nt][3] * scale;
            if (diag) {
                if (col     > rq0) v0 = -1e30f;
                if (col + 1 > rq0) v1 = -1e30f;
                if (col     > rq1) v2 = -1e30f;
                if (col + 1 > rq1) v3 = -1e30f;
            }
            Ss[rq0 * SS_STRIDE + col]     = v0;
            Ss[rq0 * SS_STRIDE + col + 1] = v1;
            Ss[rq1 * SS_STRIDE + col]     = v2;
            Ss[rq1 * SS_STRIDE + col + 1] = v3;
        }
        __syncthreads();

        // --- Online softmax (4 threads per row) ---
        float mx = -1e30f;
#pragma unroll
        for (int c = 0; c < 16; ++c)
            mx = fmaxf(mx, Ss[row * SS_STRIDE + part * 16 + c]);
        mx = fmaxf(mx, __shfl_xor_sync(0xffffffffu, mx, 1));
        mx = fmaxf(mx, __shfl_xor_sync(0xffffffffu, mx, 2));
        float m_old = mrow[row];
        float m_new = fmaxf(m_old, mx);
        float sum = 0.f;
#pragma unroll
        for (int c = 0; c < 16; ++c) {
            float p = __expf(Ss[row * SS_STRIDE + part * 16 + c] - m_new);
            Ss[row * SS_STRIDE + part * 16 + c] = p;
            sum += p;
        }
        sum += __shfl_xor_sync(0xffffffffu, sum, 1);
        sum += __shfl_xor_sync(0xffffffffu, sum, 2);
        if (part == 0) {
            float alpha = __expf(m_old - m_new);
            arow[row] = alpha;
            mrow[row] = m_new;
            lrow[row] = lrow[row] * alpha + sum;
        }
        __syncthreads();

        // --- Rescale O, accumulate P @ V via bf16 MMA ---
        float al0 = arow[rq0], al1 = arow[rq1];
#pragma unroll
        for (int nt = 0; nt < 8; nt++) {
            o[nt][0] *= al0; o[nt][1] *= al0;
            o[nt][2] *= al1; o[nt][3] *= al1;
        }

#pragma unroll
        for (int kc = 0; kc < 4; kc++) {
            int ka = 16 * kc + (lc << 1);
            float2 p00 = *(float2*)&Ss[rq0 * SS_STRIDE + ka];
            float2 p01 = *(float2*)&Ss[rq0 * SS_STRIDE + ka + 8];
            float2 p10 = *(float2*)&Ss[rq1 * SS_STRIDE + ka];
            float2 p11 = *(float2*)&Ss[rq1 * SS_STRIDE + ka + 8];
            uint32_t aH[4], aL[4];
            split_pair(p00.x, p00.y, aH[0], aL[0]);
            split_pair(p10.x, p10.y, aH[1], aL[1]);
            split_pair(p01.x, p01.y, aH[2], aL[2]);
            split_pair(p11.x, p11.y, aH[3], aL[3]);
#pragma unroll
            for (int nt = 0; nt < 8; nt++) {
                int nn = h0c + nt * 8 + lr;
                int kpb = 8 * kc + lc;
                uint32_t bH[2] = {VsH[kpb * VS_STRIDE + nn], VsH[(kpb + 4) * VS_STRIDE + nn]};
                uint32_t bL[2] = {VsL[kpb * VS_STRIDE + nn], VsL[(kpb + 4) * VS_STRIDE + nn]};
                mma_bf16(o[nt], aH, bH);
                mma_bf16(o[nt], aH, bL);
                mma_bf16(o[nt], aL, bH);
            }
        }
    }

    // --- Normalize, write (B,T,N,H) ---
    int rq0 = r0 + lr, rq1 = r0 + 8 + lr;
    float li0 = 1.f / lrow[rq0], li1 = 1.f / lrow[rq1];
#pragma unroll
    for (int nt = 0; nt < 8; nt++) {
        int col = h0c + nt * 8 + (lc << 1);
        float* d0 = Og + (((size_t)(b * T_ + qt * 64 + rq0)) * NH + n) * HD + col;
        float* d1 = Og + (((size_t)(b * T_ + qt * 64 + rq1)) * NH + n) * HD + col;
        *(float2*)d0 = make_float2(o[nt][0] * li0, o[nt][1] * li0);
        *(float2*)d1 = make_float2(o[nt][2] * li1, o[nt][3] * li1);
    }
}

// ============================================================================
// Launch
// ============================================================================
extern "C" void kernel_launch(void* const* d_in, const int* in_sizes, int n_in,
                              void* d_out, int out_size)
{
    const float* Xq  = (const float*)d_in[0];
    const float* Xkv = (const float*)d_in[1];
    const int* qpos  = (const int*)d_in[2];
    const int* kvpos = (const int*)d_in[3];
    const float* Wq  = (const float*)d_in[4];
    const float* Wk  = (const float*)d_in[5];
    const float* Wv  = (const float*)d_in[6];
    const float* Wo  = (const float*)d_in[7];
    float* out = (float*)d_out;

    float *pQ, *pK, *pV, *pA;
    cudaGetSymbolAddress((void**)&pQ, g_Q);
    cudaGetSymbolAddress((void**)&pK, g_K);
    cudaGetSymbolAddress((void**)&pV, g_V);
    cudaGetSymbolAddress((void**)&pA, g_attn);

    cudaFuncSetAttribute(flash_kernel,
                         cudaFuncAttributeMaxDynamicSharedMemorySize,
                         FLASH_SMEM_BYTES);

    int M = B_ * T_;  // 4096

    // Projections (3xTF32 tensor cores, fp32-accurate)
    tf32_gemm_kernel<<<dim3((NH * HD) / 128, M / 128), 256>>>(Xq, Wq, pQ, M, NH * HD, D_);
    tf32_gemm_kernel<<<dim3((KH * HD) / 128, M / 128), 256>>>(Xkv, Wk, pK, M, KH * HD, D_);
    tf32_gemm_kernel<<<dim3((KH * HD) / 128, M / 128), 256>>>(Xkv, Wv, pV, M, KH * HD, D_);

    // RoPE
    int totQ = B_ * T_ * NH * 64;
    rope_kernel<<<(totQ + 255) / 256, 256>>>(pQ, qpos, NH, totQ);
    int totK = B_ * T_ * KH * 64;
    rope_kernel<<<(totK + 255) / 256, 256>>>(pK, kvpos, KH, totK);

    // Tensor-core causal flash attention
    flash_kernel<<<dim3(T_ / 64, NH, B_), 256, FLASH_SMEM_BYTES>>>(pQ, pK, pV, pA);

    // Output projection (3xTF32 tensor cores)
    tf32_gemm_kernel<<<dim3(D_ / 128, M / 128), 256>>>(pA, Wo, out, M, D_, NH * HD);
}

// round 6
// speedup vs baseline: 2.6571x; 1.4876x over previous
#include <cuda_runtime.h>
#include <cuda_bf16.h>
#include <math.h>
#include <stdint.h>

#define B_ 2
#define T_ 2048
#define D_ 2048
#define NH 16
#define KH 4
#define HD 128

// Scratch (static device globals — no allocation allowed)
__device__ float g_Q[(size_t)B_ * T_ * NH * HD];     // (B,T,N,H)
__device__ float g_K[(size_t)B_ * T_ * KH * HD];     // (B,T,K,H)
__device__ float g_V[(size_t)B_ * T_ * KH * HD];     // (B,T,K,H)
__device__ float g_attn[(size_t)B_ * T_ * NH * HD];  // (B,T,N,H)

// ============================================================================
// Helpers
// ============================================================================
// Split (a,b) into hi/lo bf16x2 words: hi.x=bf16(a), hi.y=bf16(b); lo = residual.
__device__ __forceinline__ void split_pair(float a, float b, uint32_t& hi, uint32_t& lo) {
    __nv_bfloat16 ha = __float2bfloat16_rn(a);
    __nv_bfloat16 hb = __float2bfloat16_rn(b);
    float ra = a - __bfloat162float(ha);
    float rb = b - __bfloat162float(hb);
    __nv_bfloat162 h2;
    h2.x = ha; h2.y = hb;
    __nv_bfloat162 l2 = __floats2bfloat162_rn(ra, rb);
    hi = *reinterpret_cast<uint32_t*>(&h2);
    lo = *reinterpret_cast<uint32_t*>(&l2);
}

__device__ __forceinline__ void mma_bf16(float* d, const uint32_t* a, const uint32_t* b) {
    asm volatile(
        "mma.sync.aligned.m16n8k16.row.col.f32.bf16.bf16.f32 "
        "{%0,%1,%2,%3}, {%4,%5,%6,%7}, {%8,%9}, {%0,%1,%2,%3};\n"
        : "+f"(d[0]), "+f"(d[1]), "+f"(d[2]), "+f"(d[3])
        : "r"(a[0]), "r"(a[1]), "r"(a[2]), "r"(a[3]), "r"(b[0]), "r"(b[1]));
}

// ============================================================================
// bf16 hi/lo 3-product GEMM: C[M,N] = A[M,Kd] * B[Kd,N], row-major fp32 in/out.
// Split to bf16x2 hi/lo ONCE at smem store; inner loop = pure LDS + HMMA.
// 128x128 block tile, BK=32, 256 threads (8 warps 4x2), warp tile 32x64.
// Requires M%128==0, N%128==0, Kd%32==0.
// Smem words: AsH/AsL [2][128*20], BsH/BsL [2][16*136] = 18944 w = 75776 B.
// ============================================================================
#define GA 20    // A row stride (words): (20r+c)%32 all-distinct for frag loads
#define GB 136   // B kp stride (words): 136%32=8 -> (8lc+lr)%32 all-distinct
#define GEMM_SMEM_BYTES ((2 * 128 * GA * 2 + 2 * 16 * GB * 2) * 4)

__global__ void __launch_bounds__(256) bf16_gemm_kernel(
    const float* __restrict__ A, const float* __restrict__ Bm,
    float* __restrict__ C, int M, int N, int Kd)
{
    extern __shared__ uint32_t gs[];
    uint32_t* AsH = gs;                      // [2][128*GA]
    uint32_t* AsL = AsH + 2 * 128 * GA;
    uint32_t* BsH = AsL + 2 * 128 * GA;      // [2][16*GB]
    uint32_t* BsL = BsH + 2 * 16 * GB;

    int bm = blockIdx.y * 128, bn = blockIdx.x * 128;
    int tid = threadIdx.x, warp = tid >> 5, lane = tid & 31;
    int wm = warp & 3, wn = warp >> 2;
    int m0 = wm * 32, n0 = wn * 64;
    int lr = lane >> 2, lc = lane & 3;

    float acc[2][8][4];
#pragma unroll
    for (int mt = 0; mt < 2; mt++)
#pragma unroll
        for (int nt = 0; nt < 8; nt++)
#pragma unroll
            for (int r = 0; r < 4; r++) acc[mt][nt][r] = 0.f;

    // Prefetch registers: A 4x float4, B 2x (pair of float4)
    float4 pa[4];
    float4 pb0[2], pb1[2];

    auto load_regs = [&](int k0) {
#pragma unroll
        for (int t = 0; t < 4; t++) {
            int i = tid + t * 256;
            int r = i >> 3, c4 = (i & 7) << 2;      // 128 rows x 32 k
            pa[t] = *(const float4*)(A + (size_t)(bm + r) * Kd + k0 + c4);
        }
#pragma unroll
        for (int t = 0; t < 2; t++) {
            int i = tid + t * 256;
            int kp = i >> 5, n4 = (i & 31) << 2;    // 16 kp x 128 n
            const float* p0 = Bm + (size_t)(k0 + 2 * kp) * N + bn + n4;
            pb0[t] = *(const float4*)p0;
            pb1[t] = *(const float4*)(p0 + N);
        }
    };

    auto store_stage = [&](int stage) {
        uint32_t* aH = AsH + stage * 128 * GA;
        uint32_t* aL = AsL + stage * 128 * GA;
        uint32_t* bH = BsH + stage * 16 * GB;
        uint32_t* bL = BsL + stage * 16 * GB;
#pragma unroll
        for (int t = 0; t < 4; t++) {
            int i = tid + t * 256;
            int r = i >> 3, c4 = (i & 7) << 2;
            uint32_t h0, l0, h1, l1;
            split_pair(pa[t].x, pa[t].y, h0, l0);
            split_pair(pa[t].z, pa[t].w, h1, l1);
            int p = r * GA + (c4 >> 1);
            aH[p] = h0; aH[p + 1] = h1;
            aL[p] = l0; aL[p + 1] = l1;
        }
#pragma unroll
        for (int t = 0; t < 2; t++) {
            int i = tid + t * 256;
            int kp = i >> 5, n4 = (i & 31) << 2;
            float ev[4] = {pb0[t].x, pb0[t].y, pb0[t].z, pb0[t].w};
            float ov[4] = {pb1[t].x, pb1[t].y, pb1[t].z, pb1[t].w};
#pragma unroll
            for (int j = 0; j < 4; j++) {
                uint32_t hh, ll;
                split_pair(ev[j], ov[j], hh, ll);   // {B[2kp][n], B[2kp+1][n]}
                bH[kp * GB + n4 + j] = hh;
                bL[kp * GB + n4 + j] = ll;
            }
        }
    };

    int nK = Kd >> 5;
    load_regs(0);
    store_stage(0);
    __syncthreads();

    for (int kc = 0; kc < nK; kc++) {
        int stage = kc & 1;
        if (kc + 1 < nK) load_regs((kc + 1) << 5);

        const uint32_t* aH = AsH + stage * 128 * GA;
        const uint32_t* aL = AsL + stage * 128 * GA;
        const uint32_t* bH = BsH + stage * 16 * GB;
        const uint32_t* bL = BsL + stage * 16 * GB;

#pragma unroll
        for (int ks = 0; ks < 2; ks++) {
            uint32_t fah[2][4], fal[2][4], fbh[8][2], fbl[8][2];
#pragma unroll
            for (int mt = 0; mt < 2; mt++) {
                int ra = (m0 + mt * 16 + lr) * GA + ks * 8 + lc;
                fah[mt][0] = aH[ra];              fah[mt][1] = aH[ra + 8 * GA];
                fah[mt][2] = aH[ra + 4];          fah[mt][3] = aH[ra + 8 * GA + 4];
                fal[mt][0] = aL[ra];              fal[mt][1] = aL[ra + 8 * GA];
                fal[mt][2] = aL[ra + 4];          fal[mt][3] = aL[ra + 8 * GA + 4];
            }
#pragma unroll
            for (int nt = 0; nt < 8; nt++) {
                int kb = (ks * 8 + lc) * GB + n0 + nt * 8 + lr;
                fbh[nt][0] = bH[kb]; fbh[nt][1] = bH[kb + 4 * GB];
                fbl[nt][0] = bL[kb]; fbl[nt][1] = bL[kb + 4 * GB];
            }
#pragma unroll
            for (int mt = 0; mt < 2; mt++)
#pragma unroll
                for (int nt = 0; nt < 8; nt++) {
                    mma_bf16(acc[mt][nt], fah[mt], fbh[nt]);  // hi*hi
                    mma_bf16(acc[mt][nt], fah[mt], fbl[nt]);  // hi*lo
                    mma_bf16(acc[mt][nt], fal[mt], fbh[nt]);  // lo*hi
                }
        }

        if (kc + 1 < nK) store_stage(stage ^ 1);
        __syncthreads();
    }

    // Epilogue
#pragma unroll
    for (int mt = 0; mt < 2; mt++) {
        int row = bm + m0 + mt * 16 + lr;
#pragma unroll
        for (int nt = 0; nt < 8; nt++) {
            int col = bn + n0 + nt * 8 + (lc << 1);
            *(float2*)(C + (size_t)row * N + col) = make_float2(acc[mt][nt][0], acc[mt][nt][1]);
            *(float2*)(C + (size_t)(row + 8) * N + col) = make_float2(acc[mt][nt][2], acc[mt][nt][3]);
        }
    }
}

// ============================================================================
// RoPE (unchanged)
// ============================================================================
__global__ void rope_kernel(float* __restrict__ x, const int* __restrict__ pos,
                            int heads, int total)
{
    int idx = blockIdx.x * blockDim.x + threadIdx.x;
    if (idx >= total) return;
    int i = idx & 63;
    int rem = idx >> 6;
    int h = rem % heads;
    int bt = rem / heads;

    float p = (float)pos[bt];
    float frac = (float)(2 * i) / 128.f;
    float ts = powf(10000.f, frac);
    float ang = p / ts;
    float s, c;
    sincosf(ang, &s, &c);

    float* base = x + ((size_t)bt * heads + h) * HD;
    float x1 = base[i], x2 = base[i + 64];
    base[i]      = x1 * c - x2 * s;
    base[i + 64] = x2 * c + x1 * s;
}

// ============================================================================
// Tensor-core causal flash attention (bf16 hi/lo 3-product MMA) — R5, passing.
// ============================================================================
#define QS_STRIDE 68
#define VS_STRIDE 132
#define SS_STRIDE 66
#define FLASH_SMEM_BYTES ((4 * 64 * QS_STRIDE + 2 * 32 * VS_STRIDE + 64 * SS_STRIDE + 192) * 4)

__global__ void __launch_bounds__(256) flash_kernel(
    const float* __restrict__ Q, const float* __restrict__ Kg,
    const float* __restrict__ Vg, float* __restrict__ Og)
{
    extern __shared__ uint32_t smw[];
    uint32_t* QsH = smw;
    uint32_t* QsL = QsH + 64 * QS_STRIDE;
    uint32_t* KsH = QsL + 64 * QS_STRIDE;
    uint32_t* KsL = KsH + 64 * QS_STRIDE;
    uint32_t* VsH = KsL + 64 * QS_STRIDE;
    uint32_t* VsL = VsH + 32 * VS_STRIDE;
    float* Ss   = (float*)(VsL + 32 * VS_STRIDE);
    float* mrow = Ss + 64 * SS_STRIDE;
    float* lrow = mrow + 64;
    float* arow = lrow + 64;

    int qt = blockIdx.x, n = blockIdx.y, b = blockIdx.z;
    int kvh = n >> 2;
    int tid = threadIdx.x, lane = tid & 31, warp = tid >> 5;
    int wq = warp & 3, wc = warp >> 2;
    int lr = lane >> 2, lc = lane & 3;
    const float scale = 0.08838834764831844f;  // 1/sqrt(128)

    int r0 = wq * 16;
    int n0 = wc * 32;
    int h0c = wc * 64;

    for (int i = tid; i < 64 * 32; i += 256) {
        int r = i >> 5, c4 = (i & 31) << 2;
        const float* src = Q + (((size_t)(b * T_ + qt * 64 + r)) * NH + n) * HD + c4;
        float4 v = *(const float4*)src;
        uint32_t h0, l0, h1, l1;
        split_pair(v.x, v.y, h0, l0);
        split_pair(v.z, v.w, h1, l1);
        int p = c4 >> 1;
        QsH[r * QS_STRIDE + p] = h0; QsH[r * QS_STRIDE + p + 1] = h1;
        QsL[r * QS_STRIDE + p] = l0; QsL[r * QS_STRIDE + p + 1] = l1;
    }
    if (tid < 64) { mrow[tid] = -1e30f; lrow[tid] = 0.f; }

    float o[8][4];
#pragma unroll
    for (int nt = 0; nt < 8; nt++)
#pragma unroll
        for (int r = 0; r < 4; r++) o[nt][r] = 0.f;

    int row = tid >> 2, part = tid & 3;

    for (int kt = 0; kt <= qt; ++kt) {
        __syncthreads();

        for (int i = tid; i < 64 * 32; i += 256) {
            int r = i >> 5, c4 = (i & 31) << 2;
            size_t g = (((size_t)(b * T_ + kt * 64 + r)) * KH + kvh) * HD + c4;
            float4 v = *(const float4*)(Kg + g);
            uint32_t h0, l0, h1, l1;
            split_pair(v.x, v.y, h0, l0);
            split_pair(v.z, v.w, h1, l1);
            int p = c4 >> 1;
            KsH[r * QS_STRIDE + p] = h0; KsH[r * QS_STRIDE + p + 1] = h1;
            KsL[r * QS_STRIDE + p] = l0; KsL[r * QS_STRIDE + p + 1] = l1;
        }
        for (int i = tid; i < 32 * 32; i += 256) {
            int kp = i >> 5, h4 = (i & 31) << 2;
            size_t g0 = (((size_t)(b * T_ + kt * 64 + 2 * kp)) * KH + kvh) * HD + h4;
            size_t g1 = g0 + (size_t)KH * HD;
            float4 va = *(const float4*)(Vg + g0);
            float4 vb = *(const float4*)(Vg + g1);
            float av[4] = {va.x, va.y, va.z, va.w};
            float bv[4] = {vb.x, vb.y, vb.z, vb.w};
#pragma unroll
            for (int j = 0; j < 4; j++) {
                uint32_t hh, ll;
                split_pair(av[j], bv[j], hh, ll);
                VsH[kp * VS_STRIDE + h4 + j] = hh;
                VsL[kp * VS_STRIDE + h4 + j] = ll;
            }
        }
        __syncthreads();

        float s[4][4];
#pragma unroll
        for (int nt = 0; nt < 4; nt++)
#pragma unroll
            for (int r = 0; r < 4; r++) s[nt][r] = 0.f;

#pragma unroll
        for (int kc = 0; kc < 8; kc++) {
            int pa = 8 * kc + lc;
            int ra = (r0 + lr) * QS_STRIDE, rb = (r0 + 8 + lr) * QS_STRIDE;
            uint32_t aH[4], aL[4];
            aH[0] = QsH[ra + pa];     aH[1] = QsH[rb + pa];
            aH[2] = QsH[ra + pa + 4]; aH[3] = QsH[rb + pa + 4];
            aL[0] = QsL[ra + pa];     aL[1] = QsL[rb + pa];
            aL[2] = QsL[ra + pa + 4]; aL[3] = QsL[rb + pa + 4];
#pragma unroll
            for (int nt = 0; nt < 4; nt++) {
                int nn = (n0 + nt * 8 + lr) * QS_STRIDE;
                uint32_t bH[2] = {KsH[nn + pa], KsH[nn + pa + 4]};
                uint32_t bL[2] = {KsL[nn + pa], KsL[nn + pa + 4]};
                mma_bf16(s[nt], aH, bH);
                mma_bf16(s[nt], aH, bL);
                mma_bf16(s[nt], aL, bH);
            }
        }

        bool diag = (kt == qt);
        int rq0 = r0 + lr, rq1 = r0 + 8 + lr;
#pragma unroll
        for (int nt = 0; nt < 4; nt++) {
            int col = n0 + nt * 8 + (lc << 1);
            float v0 = s[nt][0] * scale, v1 = s[nt][1] * scale;
            float v2 = s[nt][2] * scale, v3 = s[nt][3] * scale;
            if (diag) {
                if (col     > rq0) v0 = -1e30f;
                if (col + 1 > rq0) v1 = -1e30f;
                if (col     > rq1) v2 = -1e30f;
                if (col + 1 > rq1) v3 = -1e30f;
            }
            Ss[rq0 * SS_STRIDE + col]     = v0;
            Ss[rq0 * SS_STRIDE + col + 1] = v1;
            Ss[rq1 * SS_STRIDE + col]     = v2;
            Ss[rq1 * SS_STRIDE + col + 1] = v3;
        }
        __syncthreads();

        float mx = -1e30f;
#pragma unroll
        for (int c = 0; c < 16; ++c)
            mx = fmaxf(mx, Ss[row * SS_STRIDE + part * 16 + c]);
        mx = fmaxf(mx, __shfl_xor_sync(0xffffffffu, mx, 1));
        mx = fmaxf(mx, __shfl_xor_sync(0xffffffffu, mx, 2));
        float m_old = mrow[row];
        float m_new = fmaxf(m_old, mx);
        float sum = 0.f;
#pragma unroll
        for (int c = 0; c < 16; ++c) {
            float p = __expf(Ss[row * SS_STRIDE + part * 16 + c] - m_new);
            Ss[row * SS_STRIDE + part * 16 + c] = p;
            sum += p;
        }
        sum += __shfl_xor_sync(0xffffffffu, sum, 1);
        sum += __shfl_xor_sync(0xffffffffu, sum, 2);
        if (part == 0) {
            float alpha = __expf(m_old - m_new);
            arow[row] = alpha;
            mrow[row] = m_new;
            lrow[row] = lrow[row] * alpha + sum;
        }
        __syncthreads();

        float al0 = arow[rq0], al1 = arow[rq1];
#pragma unroll
        for (int nt = 0; nt < 8; nt++) {
            o[nt][0] *= al0; o[nt][1] *= al0;
            o[nt][2] *= al1; o[nt][3] *= al1;
        }

#pragma unroll
        for (int kc = 0; kc < 4; kc++) {
            int ka = 16 * kc + (lc << 1);
            float2 p00 = *(float2*)&Ss[rq0 * SS_STRIDE + ka];
            float2 p01 = *(float2*)&Ss[rq0 * SS_STRIDE + ka + 8];
            float2 p10 = *(float2*)&Ss[rq1 * SS_STRIDE + ka];
            float2 p11 = *(float2*)&Ss[rq1 * SS_STRIDE + ka + 8];
            uint32_t aH[4], aL[4];
            split_pair(p00.x, p00.y, aH[0], aL[0]);
            split_pair(p10.x, p10.y, aH[1], aL[1]);
            split_pair(p01.x, p01.y, aH[2], aL[2]);
            split_pair(p11.x, p11.y, aH[3], aL[3]);
#pragma unroll
            for (int nt = 0; nt < 8; nt++) {
                int nn = h0c + nt * 8 + lr;
                int kpb = 8 * kc + lc;
                uint32_t bH[2] = {VsH[kpb * VS_STRIDE + nn], VsH[(kpb + 4) * VS_STRIDE + nn]};
                uint32_t bL[2] = {VsL[kpb * VS_STRIDE + nn], VsL[(kpb + 4) * VS_STRIDE + nn]};
                mma_bf16(o[nt], aH, bH);
                mma_bf16(o[nt], aH, bL);
                mma_bf16(o[nt], aL, bH);
            }
        }
    }

    int rq0 = r0 + lr, rq1 = r0 + 8 + lr;
    float li0 = 1.f / lrow[rq0], li1 = 1.f / lrow[rq1];
#pragma unroll
    for (int nt = 0; nt < 8; nt++) {
        int col = h0c + nt * 8 + (lc << 1);
        float* d0 = Og + (((size_t)(b * T_ + qt * 64 + rq0)) * NH + n) * HD + col;
        float* d1 = Og + (((size_t)(b * T_ + qt * 64 + rq1)) * NH + n) * HD + col;
        *(float2*)d0 = make_float2(o[nt][0] * li0, o[nt][1] * li0);
        *(float2*)d1 = make_float2(o[nt][2] * li1, o[nt][3] * li1);
    }
}

// ============================================================================
// Launch
// ============================================================================
extern "C" void kernel_launch(void* const* d_in, const int* in_sizes, int n_in,
                              void* d_out, int out_size)
{
    const float* Xq  = (const float*)d_in[0];
    const float* Xkv = (const float*)d_in[1];
    const int* qpos  = (const int*)d_in[2];
    const int* kvpos = (const int*)d_in[3];
    const float* Wq  = (const float*)d_in[4];
    const float* Wk  = (const float*)d_in[5];
    const float* Wv  = (const float*)d_in[6];
    const float* Wo  = (const float*)d_in[7];
    float* out = (float*)d_out;

    float *pQ, *pK, *pV, *pA;
    cudaGetSymbolAddress((void**)&pQ, g_Q);
    cudaGetSymbolAddress((void**)&pK, g_K);
    cudaGetSymbolAddress((void**)&pV, g_V);
    cudaGetSymbolAddress((void**)&pA, g_attn);

    cudaFuncSetAttribute(flash_kernel,
                         cudaFuncAttributeMaxDynamicSharedMemorySize,
                         FLASH_SMEM_BYTES);
    cudaFuncSetAttribute(bf16_gemm_kernel,
                         cudaFuncAttributeMaxDynamicSharedMemorySize,
                         GEMM_SMEM_BYTES);

    int M = B_ * T_;  // 4096

    // Projections (bf16 hi/lo 3-product tensor cores)
    bf16_gemm_kernel<<<dim3((NH * HD) / 128, M / 128), 256, GEMM_SMEM_BYTES>>>(
        Xq, Wq, pQ, M, NH * HD, D_);
    bf16_gemm_kernel<<<dim3((KH * HD) / 128, M / 128), 256, GEMM_SMEM_BYTES>>>(
        Xkv, Wk, pK, M, KH * HD, D_);
    bf16_gemm_kernel<<<dim3((KH * HD) / 128, M / 128), 256, GEMM_SMEM_BYTES>>>(
        Xkv, Wv, pV, M, KH * HD, D_);

    // RoPE
    int totQ = B_ * T_ * NH * 64;
    rope_kernel<<<(totQ + 255) / 256, 256>>>(pQ, qpos, NH, totQ);
    int totK = B_ * T_ * KH * 64;
    rope_kernel<<<(totK + 255) / 256, 256>>>(pK, kvpos, KH, totK);

    // Tensor-core causal flash attention
    flash_kernel<<<dim3(T_ / 64, NH, B_), 256, FLASH_SMEM_BYTES>>>(pQ, pK, pV, pA);

    // Output projection
    bf16_gemm_kernel<<<dim3(D_ / 128, M / 128), 256, GEMM_SMEM_BYTES>>>(
        pA, Wo, out, M, D_, NH * HD);
}